// round 15
// baseline (speedup 1.0000x reference)
#include <cuda_runtime.h>
#include <cuda_fp16.h>
#include <math.h>
#include <stdint.h>

// ============================================================================
// Causal MHA, sm_103.
// Kernel 0: convert K,V fp32 -> fp16 head-major scratch; reset worklist+flags.
// Kernel 1: ONE persistent kernel. Ordered worklist of 4864 units:
//   [0,256)      compute items bh<16 (qt descending, heavy first)
//   [256,2688)   interleaved: 256 compute items bh>=16 + 2176 scale tiles bh<16
//   [2688,4864)  scale tiles bh>=16
// Compute items stage UNNORMALIZED exp(S) block-tiled + set done-flag.
// Scale tiles wait on their item's flag, then stream stage*1/l -> fp32 attn.
// ============================================================================

namespace {
constexpr int kS = 2048, kE = 1024;
constexpr int NQT = 16;
constexpr int NTOT = 4864;                       // 512 compute + 4352 scale
constexpr long long OUT_ELEMS  = 4194304LL;
constexpr long long ATTN_ELEMS = 134217728LL;

constexpr int QSTR = 72;                         // fp16 elems per row (144B)
constexpr int OFF_Q  = 0;                        // Q [128][72] fp16 (18432B)
constexpr int KVBUF  = 18432;                    // one K+V buffer: 2*[64][72] fp16
constexpr int OFF_KV0 = 18432;                   // 3 buffers
constexpr int OFF_L  = 18432 * 4;                // 73728
constexpr int SMEM_BYTES = OFF_L + 512;          // 74240
}  // namespace

__device__ float g_rinv[32 * 2048];              // per (bh,row) 1/l
__device__ __half g_pstage[ATTN_ELEMS];          // block-tiled 8x8=128B blocks
__device__ __half g_k16[32 * 2048 * 64];         // fp16 K head-major [bh][s][64]
__device__ __half g_v16[32 * 2048 * 64];
__device__ int g_ctr;                            // worklist counter
__device__ int g_done[512];                      // per (qt*32+bh) completion flag

__device__ __forceinline__ uint32_t smem_u32(const void* p) {
    uint32_t a;
    asm("{ .reg .u64 t; cvta.to.shared.u64 t, %1; cvt.u32.u64 %0, t; }" : "=r"(a) : "l"(p));
    return a;
}
__device__ __forceinline__ void ldsm4(uint32_t r[4], uint32_t addr) {
    asm volatile("ldmatrix.sync.aligned.m8n8.x4.shared.b16 {%0,%1,%2,%3}, [%4];"
                 : "=r"(r[0]), "=r"(r[1]), "=r"(r[2]), "=r"(r[3]) : "r"(addr));
}
__device__ __forceinline__ void ldsm4t(uint32_t r[4], uint32_t addr) {
    asm volatile("ldmatrix.sync.aligned.m8n8.x4.trans.shared.b16 {%0,%1,%2,%3}, [%4];"
                 : "=r"(r[0]), "=r"(r[1]), "=r"(r[2]), "=r"(r[3]) : "r"(addr));
}
__device__ __forceinline__ void mma16816(float c[4], const uint32_t a[4],
                                         uint32_t b0, uint32_t b1) {
    asm("mma.sync.aligned.m16n8k16.row.col.f32.f16.f16.f32 "
        "{%0,%1,%2,%3}, {%4,%5,%6,%7}, {%8,%9}, {%0,%1,%2,%3};"
        : "+f"(c[0]), "+f"(c[1]), "+f"(c[2]), "+f"(c[3])
        : "r"(a[0]), "r"(a[1]), "r"(a[2]), "r"(a[3]), "r"(b0), "r"(b1));
}
__device__ __forceinline__ uint32_t packhf(float lo_c, float hi_c) {  // {low, high}
    uint32_t r;
    asm("cvt.rn.f16x2.f32 %0, %1, %2;" : "=r"(r) : "f"(hi_c), "f"(lo_c));
    return r;
}
__device__ __forceinline__ void cp16(uint32_t smaddr, const void* gaddr) {
    asm volatile("cp.async.cg.shared.global [%0], [%1], 16;"
                 :: "r"(smaddr), "l"(gaddr) : "memory");
}
#define CP_COMMIT() asm volatile("cp.async.commit_group;" ::: "memory")
#define CP_WAIT1()  asm volatile("cp.async.wait_group 1;" ::: "memory")
#define CP_WAIT0()  asm volatile("cp.async.wait_group 0;" ::: "memory")

__device__ __forceinline__ void issue_kv(uint32_t dst, const __half* ksrc,
                                         const __half* vsrc, int tid) {
    #pragma unroll
    for (int i = 0; i < 2; i++) {
        int c = tid + i * 256;                 // 0..511
        int r = c >> 3, seg = c & 7;
        cp16(dst + (uint32_t)(r * 144 + seg * 16), ksrc + r * 64 + seg * 8);
        cp16(dst + 9216u + (uint32_t)(r * 144 + seg * 16), vsrc + r * 64 + seg * 8);
    }
    CP_COMMIT();
}

__device__ __forceinline__ void s_gemm(float (&S)[8][4], uint32_t sb, uint32_t kvb,
                                       int wr, int arow, int akh, int brow, int bkh) {
    #pragma unroll
    for (int kb = 0; kb < 4; kb++) {
        uint32_t ah[4];
        uint32_t aoff = (uint32_t)(((wr + arow) * QSTR + kb * 16 + akh * 8) * 2);
        ldsm4(ah, sb + OFF_Q + aoff);
        #pragma unroll
        for (int jp = 0; jp < 4; jp++) {
            uint32_t boff = (uint32_t)(((jp * 16 + brow) * QSTR + kb * 16 + bkh * 8) * 2);
            uint32_t bh4[4];
            ldsm4(bh4, kvb + boff);
            mma16816(S[2 * jp + 0], ah, bh4[0], bh4[1]);
            mma16816(S[2 * jp + 1], ah, bh4[2], bh4[3]);
        }
    }
}

// ascending triangular decode: tt in [0,136) -> (qt, ct), ct <= qt
__device__ __forceinline__ void tri_decode(int tt, int& qt, int& ct) {
    qt = (int)((sqrtf(8.0f * (float)tt + 1.0f) - 1.0f) * 0.5f);
    while ((qt + 1) * (qt + 2) / 2 <= tt) qt++;
    while (qt * (qt + 1) / 2 > tt) qt--;
    ct = tt - qt * (qt + 1) / 2;
}

// ============================================================================
// Kernel 0: K,V fp32 -> fp16 head-major scratch + worklist/flag reset
// ============================================================================
__global__ __launch_bounds__(256)
void cvt_kv_kernel(const float* __restrict__ k, const float* __restrict__ v) {
    if (blockIdx.x == 0 && threadIdx.x == 0) g_ctr = 0;
    if (blockIdx.x < 2) g_done[blockIdx.x * 256 + threadIdx.x] = 0;
    int idx = blockIdx.x * 256 + threadIdx.x;    // one float4 per thread
    int d4 = idx & 15;
    int h  = (idx >> 4) & 15;
    int s  = (idx >> 8) & 2047;
    int b  = idx >> 19;
    long long src = ((long long)(b * 2048 + s)) * 1024 + h * 64 + d4 * 4;
    long long dst = ((long long)((b * 16 + h) * 2048 + s)) * 64 + d4 * 4;
    float4 x = *(const float4*)&k[src];
    float4 y = *(const float4*)&v[src];
    *(uint2*)&g_k16[dst] = make_uint2(packhf(x.x, x.y), packhf(x.z, x.w));
    *(uint2*)&g_v16[dst] = make_uint2(packhf(y.x, y.y), packhf(y.z, y.w));
}

// ============================================================================
// Kernel 1: persistent fused compute + scale
// ============================================================================
__global__ __launch_bounds__(256, 2)
void attn_fused_kernel(const float* __restrict__ q, float* __restrict__ out,
                       float* __restrict__ attn) {
    extern __shared__ char smc[];
    const uint32_t sb = smem_u32(smc);
    float* lsm = (float*)(smc + OFF_L);
    __shared__ int s_item;

    const int tid = threadIdx.x;
    const int lane = tid & 31;
    const int wid = tid >> 5;
    const int g = lane >> 2, t = lane & 3;
    const int wr = wid * 16;

    const int arow = lane & 15, akh = lane >> 4;
    const int brow = ((lane >> 4) & 1) * 8 + (lane & 7), bkh = (lane >> 3) & 1;
    const int vrow = ((lane >> 3) & 1) * 8 + (lane & 7);
    const int vcol8 = ((lane >> 4) & 1) * 8;

    for (;;) {
        if (tid == 0) s_item = atomicAdd(&g_ctr, 1);
        __syncthreads();
        const int idx = s_item;
        if (idx >= NTOT) break;

        // ---------------- decode unit ----------------
        bool is_compute;
        int qt, bh, ct = 0;
        if (idx < 256) {
            is_compute = true;
            qt = 15 - (idx >> 4);
            bh = idx & 15;
        } else if (idx < 2688) {
            int u = idx - 256;
            int grp = u / 19, rem = u - grp * 19;
            if (rem < 2) {
                is_compute = true;
                int c = grp * 2 + rem;           // 0..255
                qt = 15 - (c >> 4);
                bh = 16 + (c & 15);
            } else {
                is_compute = false;
                int s = grp * 17 + (rem - 2);    // 0..2175
                bh = s & 15;
                tri_decode(s >> 4, qt, ct);      // qt ascending: producers done
            }
        } else {
            is_compute = false;
            int s = idx - 2688;                  // 0..2175
            bh = 16 + (s & 15);
            tri_decode(s >> 4, qt, ct);
        }

        if (is_compute) {
            // ======================= COMPUTE ITEM =======================
            const int b = bh >> 4, h = bh & 15;
            const float* qb = q + (long long)b * kS * kE + h * 64;
            const __half* k16 = g_k16 + (long long)bh * kS * 64;
            const __half* v16 = g_v16 + (long long)bh * kS * 64;
            float* ob = out + (long long)b * kS * kE + h * 64;
            float* ab = attn ? attn + (long long)bh * kS * kS : nullptr;

            const long long blkb1 = ((long long)bh * 65536 +
                                     (long long)(qt * 16 + wid * 2) * 256) * 64;
            const long long blkb2 = blkb1 + 16384;

            const int nkt = 2 * qt + 2;
            const int qrow_g = qt * 128 + wr + g;

            issue_kv(sb + OFF_KV0,         k16,           v16,           tid);
            issue_kv(sb + OFF_KV0 + KVBUF, k16 + 64 * 64, v16 + 64 * 64, tid);

            #pragma unroll
            for (int i = 0; i < 8; i++) {
                int e4 = tid + i * 256;
                int r = e4 >> 4, d4 = (e4 & 15) << 2;
                float4 x = *(const float4*)&qb[(long long)(qt * 128 + r) * kE + d4];
                uint32_t off = (uint32_t)((r * QSTR + d4) * 2);
                *(uint32_t*)(smc + OFF_Q + off)     = packhf(x.x * 0.125f, x.y * 0.125f);
                *(uint32_t*)(smc + OFF_Q + off + 4) = packhf(x.z * 0.125f, x.w * 0.125f);
            }

            float O[8][4];
            #pragma unroll
            for (int nb = 0; nb < 8; nb++)
                #pragma unroll
                for (int c = 0; c < 4; c++) O[nb][c] = 0.0f;
            float lp0 = 0.0f, lp1 = 0.0f;

            for (int kt = 0; kt < nkt; kt++) {
                if (kt == nkt - 1) { CP_WAIT0(); } else { CP_WAIT1(); }
                __syncthreads();

                if (kt + 2 < nkt) {
                    const long long s0 = (long long)(kt + 2) * 64 * 64;
                    issue_kv(sb + OFF_KV0 + ((kt + 2) % 3) * KVBUF, k16 + s0, v16 + s0, tid);
                }
                const uint32_t kvb = sb + OFF_KV0 + (kt % 3) * KVBUF;

                float S[8][4];
                #pragma unroll
                for (int j = 0; j < 8; j++)
                    #pragma unroll
                    for (int c = 0; c < 4; c++) S[j][c] = 0.0f;
                s_gemm(S, sb, kvb, wr, arow, akh, brow, bkh);

                const bool need_mask = (kt * 64 + 63 > qt * 128 + wr);
                uint32_t ph[8][2];
                #pragma unroll
                for (int j = 0; j < 8; j++) {
                    const int c0 = kt * 64 + j * 8 + 2 * t;
                    float e0 = __expf(S[j][0]), e1 = __expf(S[j][1]);
                    float e2 = __expf(S[j][2]), e3 = __expf(S[j][3]);
                    if (need_mask) {
                        if (c0     > qrow_g)     e0 = 0.0f;
                        if (c0 + 1 > qrow_g)     e1 = 0.0f;
                        if (c0     > qrow_g + 8) e2 = 0.0f;
                        if (c0 + 1 > qrow_g + 8) e3 = 0.0f;
                    }
                    lp0 += e0 + e1;
                    lp1 += e2 + e3;
                    uint32_t p01 = packhf(e0, e1);
                    uint32_t p23 = packhf(e2, e3);
                    const long long cb64 = (long long)(kt * 8 + j) * 64 + lane * 2;
                    *(uint32_t*)&g_pstage[blkb1 + cb64] = p01;
                    *(uint32_t*)&g_pstage[blkb2 + cb64] = p23;
                    ph[j][0] = p01;
                    ph[j][1] = p23;
                }

                #pragma unroll
                for (int kb4 = 0; kb4 < 4; kb4++) {
                    uint32_t Ah[4] = {ph[2 * kb4][0], ph[2 * kb4][1],
                                      ph[2 * kb4 + 1][0], ph[2 * kb4 + 1][1]};
                    #pragma unroll
                    for (int np = 0; np < 4; np++) {
                        uint32_t boff = (uint32_t)(((kb4 * 16 + vrow) * QSTR + np * 16 + vcol8) * 2);
                        uint32_t vh[4];
                        ldsm4t(vh, kvb + 9216u + boff);
                        mma16816(O[2 * np + 0], Ah, vh[0], vh[1]);
                        mma16816(O[2 * np + 1], Ah, vh[2], vh[3]);
                    }
                }
            }

            lp0 += __shfl_xor_sync(0xffffffffu, lp0, 1);
            lp0 += __shfl_xor_sync(0xffffffffu, lp0, 2);
            lp1 += __shfl_xor_sync(0xffffffffu, lp1, 1);
            lp1 += __shfl_xor_sync(0xffffffffu, lp1, 2);
            __syncthreads();
            if (t == 0) {
                lsm[wr + g] = lp0;
                lsm[wr + 8 + g] = lp1;
            }
            __syncthreads();
            const float ril = 1.0f / lsm[wr + g];
            const float rih = 1.0f / lsm[wr + 8 + g];
            if (t == 0) {
                g_rinv[bh * kS + qrow_g] = ril;
                g_rinv[bh * kS + qrow_g + 8] = rih;
            }

            #pragma unroll
            for (int nb = 0; nb < 8; nb++) {
                const int c0 = nb * 8 + 2 * t;
                *(float2*)&ob[(long long)qrow_g * kE + c0] =
                    make_float2(O[nb][0] * ril, O[nb][1] * ril);
                *(float2*)&ob[(long long)(qrow_g + 8) * kE + c0] =
                    make_float2(O[nb][2] * rih, O[nb][3] * rih);
            }

            if (ab) {
                const int cz0 = nkt * 64;
                const int w4 = (kS - cz0) >> 2;
                if (w4 > 0) {
                    const float4 z4 = make_float4(0.f, 0.f, 0.f, 0.f);
                    for (int i = tid; i < 128 * w4; i += 256) {
                        int r = i / w4;
                        int c = (i - r * w4) * 4 + cz0;
                        __stcs((float4*)&ab[(long long)(qt * 128 + r) * kS + c], z4);
                    }
                }
            }
            // publish completion (release)
            __threadfence();
            __syncthreads();
            if (tid == 0) atomicExch(&g_done[qt * 32 + bh], 1);
        } else {
            // ======================= SCALE TILE =======================
            if (tid == 0) {
                while (atomicAdd(&g_done[qt * 32 + bh], 0) == 0) __nanosleep(200);
                __threadfence();                   // acquire
            }
            __syncthreads();

            if (tid < 128) lsm[tid] = g_rinv[bh * kS + qt * 128 + tid];
            __syncthreads();

            const uint4* pst4 = (const uint4*)g_pstage;
            const long long tb = (long long)bh * 65536 + (long long)qt * 16 * 256 + ct * 16;
            const long long obase = (long long)bh * kS * kS +
                                    (long long)(qt * 128) * kS + ct * 128;

            #pragma unroll
            for (int i = 0; i < 8; i++) {
                int u = tid + i * 256;             // 0..2047
                int u16 = u & 7;
                int blk = u >> 3;                  // 0..255
                int rblk = blk >> 4, cblk = blk & 15;
                int row = rblk * 8 + u16;
                const float s = lsm[row];
                uint4 hp = __ldcs(&pst4[(tb + (long long)rblk * 256 + cblk) * 8 + u16]);
                float2 f01 = __half22float2(*(const __half2*)&hp.x);
                float2 f23 = __half22float2(*(const __half2*)&hp.y);
                float2 f45 = __half22float2(*(const __half2*)&hp.z);
                float2 f67 = __half22float2(*(const __half2*)&hp.w);
                float4 o0, o1;
                o0.x = f01.x * s; o0.y = f01.y * s; o0.z = f23.x * s; o0.w = f23.y * s;
                o1.x = f45.x * s; o1.y = f45.y * s; o1.z = f67.x * s; o1.w = f67.y * s;
                float* dp = attn + obase + (long long)row * kS + cblk * 8;
                __stcs((float4*)dp, o0);
                __stcs((float4*)(dp + 4), o1);
            }
            __syncthreads();                       // lsm quiesce before next unit
        }
    }
}

extern "C" void kernel_launch(void* const* d_in, const int* in_sizes, int n_in,
                              void* d_out, int out_size) {
    const float* q = (const float*)d_in[0];
    const float* k = (const float*)d_in[1];
    const float* v = (const float*)d_in[2];
    float* out = (float*)d_out;

    float* attn = nullptr;
    if ((long long)out_size >= OUT_ELEMS + ATTN_ELEMS) attn = out + OUT_ELEMS;

    cudaFuncSetAttribute(attn_fused_kernel,
                         cudaFuncAttributeMaxDynamicSharedMemorySize, SMEM_BYTES);

    cvt_kv_kernel<<<4096, 256>>>(k, v);
    attn_fused_kernel<<<296, 256, SMEM_BYTES>>>(q, out, attn);
}

// round 16
// speedup vs baseline: 1.1437x; 1.1437x over previous
#include <cuda_runtime.h>
#include <cuda_fp16.h>
#include <math.h>
#include <stdint.h>

// ============================================================================
// Causal MHA, sm_103.
// Kernel 0: convert Q(x1/8),K,V fp32 -> fp16 head-major scratch; reset flags.
// Kernel 1: ONE persistent kernel, ordered worklist:
//   [0,512)     pass-1 items (qt,bh), heavy-first: FA pass -> O, 1/l, zeros,
//               done-flag. NO staging.
//   [512,4864)  pass-2 tiles (qt,ct,bh): wait flag, recompute S=Q*K^T on
//               tensor pipe, write normalized fp32 attn via smem (coalesced).
// ============================================================================

namespace {
constexpr int kS = 2048, kE = 1024;
constexpr int NQT = 16;
constexpr int NTOT = 4864;                       // 512 pass1 + 4352 pass2
constexpr long long OUT_ELEMS  = 4194304LL;
constexpr long long ATTN_ELEMS = 134217728LL;

constexpr int QSTR = 72;                         // fp16 elems per row (144B)
constexpr int OFF_Q  = 0;                        // Q [128][72] fp16 (18432B)
constexpr int KVBUF  = 18432;                    // one K+V buffer: 2*[64][72] fp16
constexpr int OFF_KV0 = 18432;                   // 3 buffers (pass1); 2 K-halves (pass2)
constexpr int OFF_STG = 18432 * 4;               // 73728: fp32 stage [128][68] (34816B)
constexpr int OFF_L   = OFF_STG + 34816;         // 108544
constexpr int SMEM_BYTES = OFF_L + 512;          // 109056
}  // namespace

__device__ float g_rinv[32 * 2048];              // per (bh,row) 1/l
__device__ __half g_q16[32 * 2048 * 64];         // fp16 Q*0.125 head-major [bh][s][64]
__device__ __half g_k16[32 * 2048 * 64];
__device__ __half g_v16[32 * 2048 * 64];
__device__ int g_ctr;                            // worklist counter
__device__ int g_done[512];                      // per (qt*32+bh) completion flag

// pass-2 qt order (earliest-finishing producers first) and tile-count prefix
__constant__ int c_qord[16] = {8, 9, 7, 10, 6, 11, 5, 12, 4, 13, 3, 14, 2, 15, 1, 0};
__constant__ int c_qpref[17] = {0, 288, 608, 864, 1216, 1440, 1824, 2016, 2432,
                                2592, 3040, 3168, 3648, 3744, 4256, 4320, 4352};

__device__ __forceinline__ uint32_t smem_u32(const void* p) {
    uint32_t a;
    asm("{ .reg .u64 t; cvta.to.shared.u64 t, %1; cvt.u32.u64 %0, t; }" : "=r"(a) : "l"(p));
    return a;
}
__device__ __forceinline__ void ldsm4(uint32_t r[4], uint32_t addr) {
    asm volatile("ldmatrix.sync.aligned.m8n8.x4.shared.b16 {%0,%1,%2,%3}, [%4];"
                 : "=r"(r[0]), "=r"(r[1]), "=r"(r[2]), "=r"(r[3]) : "r"(addr));
}
__device__ __forceinline__ void ldsm4t(uint32_t r[4], uint32_t addr) {
    asm volatile("ldmatrix.sync.aligned.m8n8.x4.trans.shared.b16 {%0,%1,%2,%3}, [%4];"
                 : "=r"(r[0]), "=r"(r[1]), "=r"(r[2]), "=r"(r[3]) : "r"(addr));
}
__device__ __forceinline__ void mma16816(float c[4], const uint32_t a[4],
                                         uint32_t b0, uint32_t b1) {
    asm("mma.sync.aligned.m16n8k16.row.col.f32.f16.f16.f32 "
        "{%0,%1,%2,%3}, {%4,%5,%6,%7}, {%8,%9}, {%0,%1,%2,%3};"
        : "+f"(c[0]), "+f"(c[1]), "+f"(c[2]), "+f"(c[3])
        : "r"(a[0]), "r"(a[1]), "r"(a[2]), "r"(a[3]), "r"(b0), "r"(b1));
}
__device__ __forceinline__ uint32_t packhf(float lo_c, float hi_c) {  // {low, high}
    uint32_t r;
    asm("cvt.rn.f16x2.f32 %0, %1, %2;" : "=r"(r) : "f"(hi_c), "f"(lo_c));
    return r;
}
__device__ __forceinline__ void cp16(uint32_t smaddr, const void* gaddr) {
    asm volatile("cp.async.cg.shared.global [%0], [%1], 16;"
                 :: "r"(smaddr), "l"(gaddr) : "memory");
}
#define CP_COMMIT() asm volatile("cp.async.commit_group;" ::: "memory")
#define CP_WAIT1()  asm volatile("cp.async.wait_group 1;" ::: "memory")
#define CP_WAIT0()  asm volatile("cp.async.wait_group 0;" ::: "memory")

// load a 64-row fp16 [64][64] tile into smem at `dst` (144B row stride)
__device__ __forceinline__ void issue_half_tile(uint32_t dst, const __half* src, int tid) {
    #pragma unroll
    for (int i = 0; i < 2; i++) {
        int c = tid + i * 256;                 // 0..511
        int r = c >> 3, seg = c & 7;
        cp16(dst + (uint32_t)(r * 144 + seg * 16), src + r * 64 + seg * 8);
    }
}
__device__ __forceinline__ void issue_kv(uint32_t dst, const __half* ksrc,
                                         const __half* vsrc, int tid) {
    issue_half_tile(dst, ksrc, tid);
    issue_half_tile(dst + 9216u, vsrc, tid);
    CP_COMMIT();
}

// S[j][4] += Q16(16 rows of this warp) * K16_tile(64x64)^T ; K at smem addr kvb
__device__ __forceinline__ void s_gemm(float (&S)[8][4], uint32_t sb, uint32_t kvb,
                                       int wr, int arow, int akh, int brow, int bkh) {
    #pragma unroll
    for (int kb = 0; kb < 4; kb++) {
        uint32_t ah[4];
        uint32_t aoff = (uint32_t)(((wr + arow) * QSTR + kb * 16 + akh * 8) * 2);
        ldsm4(ah, sb + OFF_Q + aoff);
        #pragma unroll
        for (int jp = 0; jp < 4; jp++) {
            uint32_t boff = (uint32_t)(((jp * 16 + brow) * QSTR + kb * 16 + bkh * 8) * 2);
            uint32_t bh4[4];
            ldsm4(bh4, kvb + boff);
            mma16816(S[2 * jp + 0], ah, bh4[0], bh4[1]);
            mma16816(S[2 * jp + 1], ah, bh4[2], bh4[3]);
        }
    }
}

// ============================================================================
// Kernel 0: Q(x1/8),K,V fp32 -> fp16 head-major scratch + flag/counter reset
// ============================================================================
__global__ __launch_bounds__(256)
void cvt_kernel(const float* __restrict__ q, const float* __restrict__ k,
                const float* __restrict__ v) {
    if (blockIdx.x == 0 && threadIdx.x == 0) g_ctr = 0;
    if (blockIdx.x < 2) g_done[blockIdx.x * 256 + threadIdx.x] = 0;
    int idx = blockIdx.x * 256 + threadIdx.x;    // one float4 per tensor per thread
    int d4 = idx & 15;
    int h  = (idx >> 4) & 15;
    int s  = (idx >> 8) & 2047;
    int b  = idx >> 19;
    long long src = ((long long)(b * 2048 + s)) * 1024 + h * 64 + d4 * 4;
    long long dst = ((long long)((b * 16 + h) * 2048 + s)) * 64 + d4 * 4;
    float4 xq = *(const float4*)&q[src];
    float4 xk = *(const float4*)&k[src];
    float4 xv = *(const float4*)&v[src];
    *(uint2*)&g_q16[dst] = make_uint2(packhf(xq.x * 0.125f, xq.y * 0.125f),
                                      packhf(xq.z * 0.125f, xq.w * 0.125f));
    *(uint2*)&g_k16[dst] = make_uint2(packhf(xk.x, xk.y), packhf(xk.z, xk.w));
    *(uint2*)&g_v16[dst] = make_uint2(packhf(xv.x, xv.y), packhf(xv.z, xv.w));
}

// ============================================================================
// Kernel 1: persistent fused pass1 (FA) + pass2 (attn recompute-and-write)
// ============================================================================
__global__ __launch_bounds__(256, 2)
void attn_fused_kernel(float* __restrict__ out, float* __restrict__ attn) {
    extern __shared__ char smc[];
    const uint32_t sb = smem_u32(smc);
    float* lsm = (float*)(smc + OFF_L);
    float* stg = (float*)(smc + OFF_STG);
    __shared__ int s_item;

    const int tid = threadIdx.x;
    const int lane = tid & 31;
    const int wid = tid >> 5;
    const int g = lane >> 2, t = lane & 3;
    const int wr = wid * 16;

    const int arow = lane & 15, akh = lane >> 4;
    const int brow = ((lane >> 4) & 1) * 8 + (lane & 7), bkh = (lane >> 3) & 1;
    const int vrow = ((lane >> 3) & 1) * 8 + (lane & 7);
    const int vcol8 = ((lane >> 4) & 1) * 8;

    for (;;) {
        if (tid == 0) s_item = atomicAdd(&g_ctr, 1);
        __syncthreads();
        const int idx = s_item;
        if (idx >= NTOT) break;

        if (idx < 512) {
            // ======================= PASS 1 ITEM =======================
            const int qt = 15 - (idx >> 5);        // heavy first
            const int bh = idx & 31;
            const int b = bh >> 4, h = bh & 15;

            const __half* q16 = g_q16 + (long long)bh * kS * 64;
            const __half* k16 = g_k16 + (long long)bh * kS * 64;
            const __half* v16 = g_v16 + (long long)bh * kS * 64;
            float* ob = out + (long long)b * kS * kE + h * 64;
            float* ab = attn ? attn + (long long)bh * kS * kS : nullptr;

            const int nkt = 2 * qt + 2;
            const int qrow_g = qt * 128 + wr + g;

            // prologue: Q tile group, then KV tiles 0 and 1
            issue_half_tile(sb + OFF_Q, q16 + (long long)(qt * 128) * 64, tid);
            issue_half_tile(sb + OFF_Q + 9216u,
                            q16 + (long long)(qt * 128 + 64) * 64, tid);
            CP_COMMIT();
            issue_kv(sb + OFF_KV0,         k16,           v16,           tid);
            issue_kv(sb + OFF_KV0 + KVBUF, k16 + 64 * 64, v16 + 64 * 64, tid);

            float O[8][4];
            #pragma unroll
            for (int nb = 0; nb < 8; nb++)
                #pragma unroll
                for (int c = 0; c < 4; c++) O[nb][c] = 0.0f;
            float lp0 = 0.0f, lp1 = 0.0f;

            for (int kt = 0; kt < nkt; kt++) {
                if (kt == nkt - 1) { CP_WAIT0(); } else { CP_WAIT1(); }
                __syncthreads();

                if (kt + 2 < nkt) {
                    const long long s0 = (long long)(kt + 2) * 64 * 64;
                    issue_kv(sb + OFF_KV0 + ((kt + 2) % 3) * KVBUF, k16 + s0, v16 + s0, tid);
                }
                const uint32_t kvb = sb + OFF_KV0 + (kt % 3) * KVBUF;

                float S[8][4];
                #pragma unroll
                for (int j = 0; j < 8; j++)
                    #pragma unroll
                    for (int c = 0; c < 4; c++) S[j][c] = 0.0f;
                s_gemm(S, sb, kvb, wr, arow, akh, brow, bkh);

                const bool need_mask = (kt * 64 + 63 > qt * 128 + wr);
                uint32_t ph[8][2];
                #pragma unroll
                for (int j = 0; j < 8; j++) {
                    const int c0 = kt * 64 + j * 8 + 2 * t;
                    float e0 = __expf(S[j][0]), e1 = __expf(S[j][1]);
                    float e2 = __expf(S[j][2]), e3 = __expf(S[j][3]);
                    if (need_mask) {
                        if (c0     > qrow_g)     e0 = 0.0f;
                        if (c0 + 1 > qrow_g)     e1 = 0.0f;
                        if (c0     > qrow_g + 8) e2 = 0.0f;
                        if (c0 + 1 > qrow_g + 8) e3 = 0.0f;
                    }
                    lp0 += e0 + e1;
                    lp1 += e2 + e3;
                    ph[j][0] = packhf(e0, e1);
                    ph[j][1] = packhf(e2, e3);
                }

                #pragma unroll
                for (int kb4 = 0; kb4 < 4; kb4++) {
                    uint32_t Ah[4] = {ph[2 * kb4][0], ph[2 * kb4][1],
                                      ph[2 * kb4 + 1][0], ph[2 * kb4 + 1][1]};
                    #pragma unroll
                    for (int np = 0; np < 4; np++) {
                        uint32_t boff = (uint32_t)(((kb4 * 16 + vrow) * QSTR + np * 16 + vcol8) * 2);
                        uint32_t vh[4];
                        ldsm4t(vh, kvb + 9216u + boff);
                        mma16816(O[2 * np + 0], Ah, vh[0], vh[1]);
                        mma16816(O[2 * np + 1], Ah, vh[2], vh[3]);
                    }
                }
            }

            lp0 += __shfl_xor_sync(0xffffffffu, lp0, 1);
            lp0 += __shfl_xor_sync(0xffffffffu, lp0, 2);
            lp1 += __shfl_xor_sync(0xffffffffu, lp1, 1);
            lp1 += __shfl_xor_sync(0xffffffffu, lp1, 2);
            __syncthreads();
            if (t == 0) {
                lsm[wr + g] = lp0;
                lsm[wr + 8 + g] = lp1;
            }
            __syncthreads();
            const float ril = 1.0f / lsm[wr + g];
            const float rih = 1.0f / lsm[wr + 8 + g];
            if (t == 0) {
                g_rinv[bh * kS + qrow_g] = ril;
                g_rinv[bh * kS + qrow_g + 8] = rih;
            }

            #pragma unroll
            for (int nb = 0; nb < 8; nb++) {
                const int c0 = nb * 8 + 2 * t;
                *(float2*)&ob[(long long)qrow_g * kE + c0] =
                    make_float2(O[nb][0] * ril, O[nb][1] * ril);
                *(float2*)&ob[(long long)(qrow_g + 8) * kE + c0] =
                    make_float2(O[nb][2] * rih, O[nb][3] * rih);
            }

            if (ab) {
                const int cz0 = nkt * 64;
                const int w4 = (kS - cz0) >> 2;
                if (w4 > 0) {
                    const float4 z4 = make_float4(0.f, 0.f, 0.f, 0.f);
                    for (int i = tid; i < 128 * w4; i += 256) {
                        int r = i / w4;
                        int c = (i - r * w4) * 4 + cz0;
                        __stcs((float4*)&ab[(long long)(qt * 128 + r) * kS + c], z4);
                    }
                }
            }
            __threadfence();
            __syncthreads();
            if (tid == 0) atomicExch(&g_done[qt * 32 + bh], 1);
        } else if (attn) {
            // ======================= PASS 2 TILE =======================
            const int s = idx - 512;               // 0..4351
            int seg = 0;
            #pragma unroll
            for (int i = 1; i < 16; i++) seg += (s >= c_qpref[i]);
            const int qt = c_qord[seg];
            const int r = s - c_qpref[seg];
            const int ct = r >> 5;
            const int bh = r & 31;

            if (tid == 0) {
                while (atomicAdd(&g_done[qt * 32 + bh], 0) == 0) __nanosleep(100);
                __threadfence();
            }
            __syncthreads();

            if (tid < 128) lsm[tid] = g_rinv[bh * kS + qt * 128 + tid];

            const __half* q16 = g_q16 + (long long)bh * kS * 64;
            const __half* k16 = g_k16 + (long long)bh * kS * 64;
            issue_half_tile(sb + OFF_Q, q16 + (long long)(qt * 128) * 64, tid);
            issue_half_tile(sb + OFF_Q + 9216u,
                            q16 + (long long)(qt * 128 + 64) * 64, tid);
            issue_half_tile(sb + OFF_KV0, k16 + (long long)(ct * 128) * 64, tid);
            issue_half_tile(sb + OFF_KV0 + KVBUF,
                            k16 + (long long)(ct * 128 + 64) * 64, tid);
            CP_COMMIT();
            CP_WAIT0();
            __syncthreads();

            float* ab = attn + (long long)bh * kS * kS;
            const int qrow_g = qt * 128 + wr + g;
            const float ril = lsm[wr + g];
            const float rih = lsm[wr + 8 + g];

            #pragma unroll
            for (int half = 0; half < 2; half++) {
                const uint32_t kvb = sb + OFF_KV0 + half * KVBUF;
                float S[8][4];
                #pragma unroll
                for (int j = 0; j < 8; j++)
                    #pragma unroll
                    for (int c = 0; c < 4; c++) S[j][c] = 0.0f;
                s_gemm(S, sb, kvb, wr, arow, akh, brow, bkh);

                const bool need_mask = (ct == qt);
                #pragma unroll
                for (int j = 0; j < 8; j++) {
                    const int cl = half * 64 + j * 8 + 2 * t;     // local col 0..127
                    const int c0 = ct * 128 + cl;
                    float p0 = __expf(S[j][0]) * ril, p1 = __expf(S[j][1]) * ril;
                    float p2 = __expf(S[j][2]) * rih, p3 = __expf(S[j][3]) * rih;
                    if (need_mask) {
                        if (c0     > qrow_g)     p0 = 0.0f;
                        if (c0 + 1 > qrow_g)     p1 = 0.0f;
                        if (c0     > qrow_g + 8) p2 = 0.0f;
                        if (c0 + 1 > qrow_g + 8) p3 = 0.0f;
                    }
                    const int cj = j * 8 + 2 * t;
                    *(float2*)&stg[(wr + g) * 68 + cj]     = make_float2(p0, p1);
                    *(float2*)&stg[(wr + 8 + g) * 68 + cj] = make_float2(p2, p3);
                }
                __syncthreads();
                // coalesced drain: 128 rows x 64 cols
                #pragma unroll
                for (int i = 0; i < 8; i++) {
                    int x = tid + i * 256;          // 0..2047
                    int row = x >> 4, c4 = (x & 15) << 2;
                    float4 val = *(float4*)&stg[row * 68 + c4];
                    __stcs((float4*)&ab[(long long)(qt * 128 + row) * kS +
                                        ct * 128 + half * 64 + c4], val);
                }
                __syncthreads();
            }
        }
    }
}

extern "C" void kernel_launch(void* const* d_in, const int* in_sizes, int n_in,
                              void* d_out, int out_size) {
    const float* q = (const float*)d_in[0];
    const float* k = (const float*)d_in[1];
    const float* v = (const float*)d_in[2];
    float* out = (float*)d_out;

    float* attn = nullptr;
    if ((long long)out_size >= OUT_ELEMS + ATTN_ELEMS) attn = out + OUT_ELEMS;

    cudaFuncSetAttribute(attn_fused_kernel,
                         cudaFuncAttributeMaxDynamicSharedMemorySize, SMEM_BYTES);

    cvt_kernel<<<4096, 256>>>(q, k, v);
    attn_fused_kernel<<<296, 256, SMEM_BYTES>>>(out, attn);
}